// round 15
// baseline (speedup 1.0000x reference)
#include <cuda_runtime.h>
#include <math.h>

#define N_NODES  50000
#define N_EDGES  800000
#define N_GRAPHS 1000
#define F_INPUT  128
#define HID      64
#define OUT_F    16
#define BN_EPS   1e-5f
#define NBLK256  ((N_NODES + 255) / 256)   // 196
#define IDX_CAP  1536                      // smem-staged CSR indices per tile

// ---------------- scratch (static device globals; no allocation) ------------
// g_deg relies on static zero-init for the first call; fill_kernel re-zeroes
// it every call (same work every call, deterministic).
__device__ float g_BA[N_NODES * HID];      // ping buffer
__device__ float g_BB[N_NODES * HID];      // pong buffer
__device__ float g_stats[3 * 2 * HID];     // per-layer sum, sumsq
__device__ float g_pooled[N_GRAPHS * HID]; // segment max
// CSR scratch
__device__ int g_deg[N_NODES];
__device__ int g_off[N_NODES + 1];
__device__ int g_cur[N_NODES];
__device__ int g_csr[N_EDGES];
__device__ int g_bsum[NBLK256];

// ---------------- helpers ---------------------------------------------------
__device__ __forceinline__ void atomicMaxF(float* addr, float val) {
    if (val >= 0.f) atomicMax((int*)addr, __float_as_int(val));
    else            atomicMin((unsigned int*)addr, __float_as_uint(val));
}
__device__ __forceinline__ void add4(float4& a, const float4 b) {
    a.x += b.x; a.y += b.y; a.z += b.z; a.w += b.w;
}

// ---------------- CSR build (R11-proven: 1 edge per thread) -----------------
__global__ void hist_kernel(const int* __restrict__ ei) {
    int e = blockIdx.x * blockDim.x + threadIdx.x;
    if (e < N_EDGES) atomicAdd(&g_deg[__ldg(&ei[N_EDGES + e])], 1);
}
// scanA: per-block degree sums (blocks < NBLK256) + init pooled/stats.
__global__ void scanA_kernel() {
    __shared__ int sh[256];
    int tid = threadIdx.x;
    int gi = blockIdx.x * 256 + tid;
    if (gi < N_GRAPHS * HID) g_pooled[gi] = -INFINITY;
    if (gi < 3 * 2 * HID) g_stats[gi] = 0.f;
    if (blockIdx.x >= NBLK256) return;
    int n = blockIdx.x * 256 + tid;
    sh[tid] = (n < N_NODES) ? g_deg[n] : 0;
    __syncthreads();
    for (int s = 128; s > 0; s >>= 1) {
        if (tid < s) sh[tid] += sh[tid + s];
        __syncthreads();
    }
    if (tid == 0) g_bsum[blockIdx.x] = sh[0];
}
__global__ void scanC_kernel() {
    __shared__ int sh[256];
    __shared__ int boff_sh;
    int tid = threadIdx.x;
    int part = 0;
    for (int j = tid; j < blockIdx.x; j += 256) part += g_bsum[j];
    sh[tid] = part;
    __syncthreads();
    for (int s = 128; s > 0; s >>= 1) {
        if (tid < s) sh[tid] += sh[tid + s];
        __syncthreads();
    }
    if (tid == 0) boff_sh = sh[0];
    __syncthreads();
    int boff = boff_sh;
    int n = blockIdx.x * 256 + tid;
    int v = (n < N_NODES) ? g_deg[n] : 0;
    sh[tid] = v;
    __syncthreads();
    for (int d = 1; d < 256; d <<= 1) {
        int t = (tid >= d) ? sh[tid - d] : 0;
        __syncthreads();
        sh[tid] += t;
        __syncthreads();
    }
    if (n < N_NODES) {
        int off = boff + sh[tid] - v;
        g_off[n] = off;
        g_cur[n] = off;
    }
    if (blockIdx.x == NBLK256 - 1 && tid == 255)
        g_off[N_NODES] = boff + sh[255];
}
__global__ void fill_kernel(const int* __restrict__ ei) {
    int e = blockIdx.x * blockDim.x + threadIdx.x;
    if (e < N_NODES) g_deg[e] = 0;      // reset for next call
    if (e >= N_EDGES) return;
    int s = __ldg(&ei[e]);
    int d = __ldg(&ei[N_EDGES + e]);
    int pos = atomicAdd(&g_cur[d], 1);
    g_csr[pos] = s;
}

// ---------------- gemm1_L0: B1 = x @ l0_w1 (128->64) ------------------------
__global__ void __launch_bounds__(128) gemm1_l0_kernel(
    const float* __restrict__ h, const float* __restrict__ w)
{
    extern __shared__ float smem[];
    float* w_sh = smem;                     // [128][64]
    float* h_sh = smem + F_INPUT * HID;     // [128][128]
    int tid = threadIdx.x;

    for (int i = tid; i < F_INPUT * HID / 4; i += 128)
        ((float4*)w_sh)[i] = ((const float4*)w)[i];

    int rowbase = blockIdx.x * 128;
    int nrows = N_NODES - rowbase; if (nrows > 128) nrows = 128;
    const float4* hbase = (const float4*)(h + (long)rowbase * F_INPUT);
    for (int i = tid; i < 128 * F_INPUT / 4; i += 128) {
        int r = i / (F_INPUT / 4);
        ((float4*)h_sh)[i] = (r < nrows) ? hbase[i] : make_float4(0.f, 0.f, 0.f, 0.f);
    }
    __syncthreads();

    int rg = tid >> 3, cg = tid & 7;
    int r0 = rg * 8, c0 = cg * 8;
    float acc[8][8];
#pragma unroll
    for (int r = 0; r < 8; r++)
#pragma unroll
        for (int j = 0; j < 8; j++) acc[r][j] = 0.f;

    for (int k = 0; k < F_INPUT; k += 4) {
        float4 av[8];
#pragma unroll
        for (int r = 0; r < 8; r++)
            av[r] = *(const float4*)&h_sh[(r0 + r) * F_INPUT + k];
#pragma unroll
        for (int kk = 0; kk < 4; kk++) {
            float4 w0 = *(const float4*)&w_sh[(k + kk) * HID + c0];
            float4 w1 = *(const float4*)&w_sh[(k + kk) * HID + c0 + 4];
#pragma unroll
            for (int r = 0; r < 8; r++) {
                float a = (kk == 0) ? av[r].x : (kk == 1) ? av[r].y
                         : (kk == 2) ? av[r].z : av[r].w;
                acc[r][0] += a * w0.x; acc[r][1] += a * w0.y;
                acc[r][2] += a * w0.z; acc[r][3] += a * w0.w;
                acc[r][4] += a * w1.x; acc[r][5] += a * w1.y;
                acc[r][6] += a * w1.z; acc[r][7] += a * w1.w;
            }
        }
    }
#pragma unroll
    for (int r = 0; r < 8; r++) {
        if (r0 + r < nrows) {
            long off = (long)(rowbase + r0 + r) * HID + c0;
            *(float4*)&g_BB[off]     = make_float4(acc[r][0], acc[r][1], acc[r][2], acc[r][3]);
            *(float4*)&g_BB[off + 4] = make_float4(acc[r][4], acc[r][5], acc[r][6], acc[r][7]);
        }
    }
}

// ---------------- layer-0 fused agg + gemm2 (smem-staged indices) -----------
__global__ void __launch_bounds__(128) agg_gemm2_l0_kernel(
    const float* __restrict__ b1, const float* __restrict__ w2,
    const float* __restrict__ b2)
{
    extern __shared__ float smem[];
    float* w_sh = smem;                 // [64][64]
    float* u_sh = smem + HID * HID;     // [128][64]
    __shared__ int idx_sh[IDX_CAP];
    __shared__ float s_sum[HID];
    __shared__ float s_sq[HID];
    int tid = threadIdx.x;

    for (int i = tid; i < HID * HID / 4; i += 128)
        ((float4*)w_sh)[i] = ((const float4*)w2)[i];
    if (tid < HID) { s_sum[tid] = 0.f; s_sq[tid] = 0.f; }

    int rowbase = blockIdx.x * 128;
    int nrows = N_NODES - rowbase; if (nrows > 128) nrows = 128;

    // stage this tile's contiguous CSR segment into smem
    int idx_begin = g_off[rowbase];
    int stage = g_off[rowbase + nrows] - idx_begin;
    if (stage > IDX_CAP) stage = IDX_CAP;
    for (int i = tid; i < stage; i += 128)
        idx_sh[i] = __ldg(&g_csr[idx_begin + i]);
    __syncthreads();

    // gather: 1024 tasks (128 rows x 8 slices), 8 per thread
    for (int it = 0; it < 8; it++) {
        int task = it * 128 + tid;
        int row = task >> 3;
        int c = (task & 7) * 8;
        float4 a0 = make_float4(0.f, 0.f, 0.f, 0.f), a1 = a0;
        if (row < nrows) {
            int node = rowbase + row;
            long base = (long)node * HID + c;
            a0 = *(const float4*)&g_BB[base];
            a1 = *(const float4*)&g_BB[base + 4];
            int p = g_off[node], end = g_off[node + 1];
            for (; p + 2 <= end; p += 2) {
                int l = p - idx_begin;
                int s0 = (l     < stage) ? idx_sh[l]     : __ldg(&g_csr[p]);
                int s1 = (l + 1 < stage) ? idx_sh[l + 1] : __ldg(&g_csr[p + 1]);
                const float4* t0 = (const float4*)(g_BB + (long)s0 * HID + c);
                const float4* t1 = (const float4*)(g_BB + (long)s1 * HID + c);
                float4 v00 = __ldg(t0), v01 = __ldg(t0 + 1);
                float4 v10 = __ldg(t1), v11 = __ldg(t1 + 1);
                add4(a0, v00); add4(a1, v01);
                add4(a0, v10); add4(a1, v11);
            }
            if (p < end) {
                int l = p - idx_begin;
                int s0 = (l < stage) ? idx_sh[l] : __ldg(&g_csr[p]);
                const float4* t0 = (const float4*)(g_BB + (long)s0 * HID + c);
                add4(a0, __ldg(t0)); add4(a1, __ldg(t0 + 1));
            }
            float4 bb0 = *(const float4*)&b1[c];
            float4 bb1 = *(const float4*)&b1[c + 4];
            a0.x = fmaxf(a0.x + bb0.x, 0.f); a0.y = fmaxf(a0.y + bb0.y, 0.f);
            a0.z = fmaxf(a0.z + bb0.z, 0.f); a0.w = fmaxf(a0.w + bb0.w, 0.f);
            a1.x = fmaxf(a1.x + bb1.x, 0.f); a1.y = fmaxf(a1.y + bb1.y, 0.f);
            a1.z = fmaxf(a1.z + bb1.z, 0.f); a1.w = fmaxf(a1.w + bb1.w, 0.f);
        }
        *(float4*)&u_sh[row * HID + c]     = a0;
        *(float4*)&u_sh[row * HID + c + 4] = a1;
    }
    __syncthreads();

    // GEMM2 (8x8 per thread)
    int rg = tid >> 3, cg = tid & 7;
    int r0 = rg * 8, c0 = cg * 8;
    float acc[8][8];
#pragma unroll
    for (int r = 0; r < 8; r++)
#pragma unroll
        for (int j = 0; j < 8; j++) acc[r][j] = 0.f;

    for (int k = 0; k < HID; k += 4) {
        float4 av[8];
#pragma unroll
        for (int r = 0; r < 8; r++)
            av[r] = *(const float4*)&u_sh[(r0 + r) * HID + k];
#pragma unroll
        for (int kk = 0; kk < 4; kk++) {
            float4 w0 = *(const float4*)&w_sh[(k + kk) * HID + c0];
            float4 w1 = *(const float4*)&w_sh[(k + kk) * HID + c0 + 4];
#pragma unroll
            for (int r = 0; r < 8; r++) {
                float a = (kk == 0) ? av[r].x : (kk == 1) ? av[r].y
                         : (kk == 2) ? av[r].z : av[r].w;
                acc[r][0] += a * w0.x; acc[r][1] += a * w0.y;
                acc[r][2] += a * w0.z; acc[r][3] += a * w0.w;
                acc[r][4] += a * w1.x; acc[r][5] += a * w1.y;
                acc[r][6] += a * w1.z; acc[r][7] += a * w1.w;
            }
        }
    }

    float4 bb0 = *(const float4*)&b2[c0];
    float4 bb1 = *(const float4*)&b2[c0 + 4];
    float ls[8] = {0,0,0,0,0,0,0,0};
    float lq[8] = {0,0,0,0,0,0,0,0};
#pragma unroll
    for (int r = 0; r < 8; r++) {
        if (r0 + r < nrows) {
            float o[8];
            o[0] = fmaxf(acc[r][0] + bb0.x, 0.f); o[1] = fmaxf(acc[r][1] + bb0.y, 0.f);
            o[2] = fmaxf(acc[r][2] + bb0.z, 0.f); o[3] = fmaxf(acc[r][3] + bb0.w, 0.f);
            o[4] = fmaxf(acc[r][4] + bb1.x, 0.f); o[5] = fmaxf(acc[r][5] + bb1.y, 0.f);
            o[6] = fmaxf(acc[r][6] + bb1.z, 0.f); o[7] = fmaxf(acc[r][7] + bb1.w, 0.f);
            long off = (long)(rowbase + r0 + r) * HID + c0;
            *(float4*)&g_BA[off]     = make_float4(o[0], o[1], o[2], o[3]);
            *(float4*)&g_BA[off + 4] = make_float4(o[4], o[5], o[6], o[7]);
#pragma unroll
            for (int j = 0; j < 8; j++) { ls[j] += o[j]; lq[j] += o[j] * o[j]; }
        }
    }
#pragma unroll
    for (int j = 0; j < 8; j++) {
        atomicAdd(&s_sum[c0 + j], ls[j]);
        atomicAdd(&s_sq[c0 + j],  lq[j]);
    }
    __syncthreads();
    if (tid < HID) {
        atomicAdd(&g_stats[tid], s_sum[tid]);
        atomicAdd(&g_stats[HID + tid], s_sq[tid]);
    }
}

// ---------------- fused layer (layers 1,2) ----------------------------------
// u = relu( aggv @ (sc⊙W1) + (1+deg_r)·(sf@W1)_c + b1_c )
// vout = relu( u @ W2 + b2 ) ; stats[layer]
template <bool IN_IS_A>
__global__ void __launch_bounds__(128) fused_layer_kernel(
    const float* __restrict__ gamma, const float* __restrict__ beta,
    const float* __restrict__ w1, const float* __restrict__ b1,
    const float* __restrict__ w2, const float* __restrict__ b2,
    int stats_layer, int layer)
{
    extern __shared__ float smem[];
    float* w_sh = smem;                 // [64][64] : W1f, later W2
    float* t_sh = smem + HID * HID;     // [128][64]: aggv, later u
    __shared__ int idx_sh[IDX_CAP];
    __shared__ float sc[HID], sf[HID], sfw1[HID];
    __shared__ float degs[128];
    __shared__ float s_sum[HID];
    __shared__ float s_sq[HID];
    int tid = threadIdx.x;

    const float* vin = IN_IS_A ? g_BA : g_BB;
    float* vout      = IN_IS_A ? g_BB : g_BA;

    if (tid < HID) {
        const float* stats = g_stats + stats_layer * 2 * HID;
        float inv_n = 1.f / (float)N_NODES;
        float mu  = stats[tid] * inv_n;
        float var = stats[HID + tid] * inv_n - mu * mu;
        float s = gamma[tid] * rsqrtf(var + BN_EPS);
        sc[tid] = s;
        sf[tid] = beta[tid] - mu * s;
        s_sum[tid] = 0.f; s_sq[tid] = 0.f;
    }
    __syncthreads();

    for (int i = tid; i < HID * HID / 4; i += 128) {
        float4 v = ((const float4*)w1)[i];
        float s = sc[i >> 4];
        v.x *= s; v.y *= s; v.z *= s; v.w *= s;
        ((float4*)w_sh)[i] = v;
    }
    if (tid < HID) {
        float b = 0.f;
#pragma unroll 8
        for (int k = 0; k < HID; k++)
            b += sf[k] * __ldg(&w1[k * HID + tid]);
        sfw1[tid] = b;
    }

    int rowbase = blockIdx.x * 128;
    int nrows = N_NODES - rowbase; if (nrows > 128) nrows = 128;

    // stage this tile's contiguous CSR segment into smem
    int idx_begin = g_off[rowbase];
    int stage = g_off[rowbase + nrows] - idx_begin;
    if (stage > IDX_CAP) stage = IDX_CAP;
    for (int i = tid; i < stage; i += 128)
        idx_sh[i] = __ldg(&g_csr[idx_begin + i]);
    __syncthreads();

    // gather RAW aggv into t_sh; record deg
    for (int it = 0; it < 8; it++) {
        int task = it * 128 + tid;
        int row = task >> 3;
        int c = (task & 7) * 8;
        float4 a0 = make_float4(0.f, 0.f, 0.f, 0.f), a1 = a0;
        if (row < nrows) {
            int node = rowbase + row;
            long base = (long)node * HID + c;
            a0 = *(const float4*)&vin[base];
            a1 = *(const float4*)&vin[base + 4];
            int p = g_off[node], end = g_off[node + 1];
            if (c == 0) degs[row] = (float)(1 + end - p);
            for (; p + 2 <= end; p += 2) {
                int l = p - idx_begin;
                int s0 = (l     < stage) ? idx_sh[l]     : __ldg(&g_csr[p]);
                int s1 = (l + 1 < stage) ? idx_sh[l + 1] : __ldg(&g_csr[p + 1]);
                const float4* t0 = (const float4*)(vin + (long)s0 * HID + c);
                const float4* t1 = (const float4*)(vin + (long)s1 * HID + c);
                float4 v00 = __ldg(t0), v01 = __ldg(t0 + 1);
                float4 v10 = __ldg(t1), v11 = __ldg(t1 + 1);
                add4(a0, v00); add4(a1, v01);
                add4(a0, v10); add4(a1, v11);
            }
            if (p < end) {
                int l = p - idx_begin;
                int s0 = (l < stage) ? idx_sh[l] : __ldg(&g_csr[p]);
                const float4* t0 = (const float4*)(vin + (long)s0 * HID + c);
                add4(a0, __ldg(t0)); add4(a1, __ldg(t0 + 1));
            }
        }
        *(float4*)&t_sh[row * HID + c]     = a0;
        *(float4*)&t_sh[row * HID + c + 4] = a1;
    }
    __syncthreads();

    int rg = tid >> 3, cg = tid & 7;
    int r0 = rg * 8, c0 = cg * 8;

    // GEMM1
    float acc[8][8];
#pragma unroll
    for (int r = 0; r < 8; r++)
#pragma unroll
        for (int j = 0; j < 8; j++) acc[r][j] = 0.f;

    for (int k = 0; k < HID; k += 4) {
        float4 av[8];
#pragma unroll
        for (int r = 0; r < 8; r++)
            av[r] = *(const float4*)&t_sh[(r0 + r) * HID + k];
#pragma unroll
        for (int kk = 0; kk < 4; kk++) {
            float4 w0 = *(const float4*)&w_sh[(k + kk) * HID + c0];
            float4 w1v = *(const float4*)&w_sh[(k + kk) * HID + c0 + 4];
#pragma unroll
            for (int r = 0; r < 8; r++) {
                float a = (kk == 0) ? av[r].x : (kk == 1) ? av[r].y
                         : (kk == 2) ? av[r].z : av[r].w;
                acc[r][0] += a * w0.x;  acc[r][1] += a * w0.y;
                acc[r][2] += a * w0.z;  acc[r][3] += a * w0.w;
                acc[r][4] += a * w1v.x; acc[r][5] += a * w1v.y;
                acc[r][6] += a * w1v.z; acc[r][7] += a * w1v.w;
            }
        }
    }
    float4 p0 = *(const float4*)&sfw1[c0];
    float4 p1 = *(const float4*)&sfw1[c0 + 4];
    float4 q0 = *(const float4*)&b1[c0];
    float4 q1 = *(const float4*)&b1[c0 + 4];
    float u[8][8];
#pragma unroll
    for (int r = 0; r < 8; r++) {
        float n = degs[r0 + r];
        u[r][0] = fmaxf(acc[r][0] + n * p0.x + q0.x, 0.f);
        u[r][1] = fmaxf(acc[r][1] + n * p0.y + q0.y, 0.f);
        u[r][2] = fmaxf(acc[r][2] + n * p0.z + q0.z, 0.f);
        u[r][3] = fmaxf(acc[r][3] + n * p0.w + q0.w, 0.f);
        u[r][4] = fmaxf(acc[r][4] + n * p1.x + q1.x, 0.f);
        u[r][5] = fmaxf(acc[r][5] + n * p1.y + q1.y, 0.f);
        u[r][6] = fmaxf(acc[r][6] + n * p1.z + q1.z, 0.f);
        u[r][7] = fmaxf(acc[r][7] + n * p1.w + q1.w, 0.f);
    }
    __syncthreads();

#pragma unroll
    for (int r = 0; r < 8; r++) {
        *(float4*)&t_sh[(r0 + r) * HID + c0]     = make_float4(u[r][0], u[r][1], u[r][2], u[r][3]);
        *(float4*)&t_sh[(r0 + r) * HID + c0 + 4] = make_float4(u[r][4], u[r][5], u[r][6], u[r][7]);
    }
    for (int i = tid; i < HID * HID / 4; i += 128)
        ((float4*)w_sh)[i] = ((const float4*)w2)[i];
    __syncthreads();

    // GEMM2
#pragma unroll
    for (int r = 0; r < 8; r++)
#pragma unroll
        for (int j = 0; j < 8; j++) acc[r][j] = 0.f;

    for (int k = 0; k < HID; k += 4) {
        float4 av[8];
#pragma unroll
        for (int r = 0; r < 8; r++)
            av[r] = *(const float4*)&t_sh[(r0 + r) * HID + k];
#pragma unroll
        for (int kk = 0; kk < 4; kk++) {
            float4 w0 = *(const float4*)&w_sh[(k + kk) * HID + c0];
            float4 w1v = *(const float4*)&w_sh[(k + kk) * HID + c0 + 4];
#pragma unroll
            for (int r = 0; r < 8; r++) {
                float a = (kk == 0) ? av[r].x : (kk == 1) ? av[r].y
                         : (kk == 2) ? av[r].z : av[r].w;
                acc[r][0] += a * w0.x;  acc[r][1] += a * w0.y;
                acc[r][2] += a * w0.z;  acc[r][3] += a * w0.w;
                acc[r][4] += a * w1v.x; acc[r][5] += a * w1v.y;
                acc[r][6] += a * w1v.z; acc[r][7] += a * w1v.w;
            }
        }
    }

    float4 bb0 = *(const float4*)&b2[c0];
    float4 bb1 = *(const float4*)&b2[c0 + 4];
    float ls[8] = {0,0,0,0,0,0,0,0};
    float lq[8] = {0,0,0,0,0,0,0,0};
#pragma unroll
    for (int r = 0; r < 8; r++) {
        if (r0 + r < nrows) {
            float o[8];
            o[0] = fmaxf(acc[r][0] + bb0.x, 0.f); o[1] = fmaxf(acc[r][1] + bb0.y, 0.f);
            o[2] = fmaxf(acc[r][2] + bb0.z, 0.f); o[3] = fmaxf(acc[r][3] + bb0.w, 0.f);
            o[4] = fmaxf(acc[r][4] + bb1.x, 0.f); o[5] = fmaxf(acc[r][5] + bb1.y, 0.f);
            o[6] = fmaxf(acc[r][6] + bb1.z, 0.f); o[7] = fmaxf(acc[r][7] + bb1.w, 0.f);
            long off = (long)(rowbase + r0 + r) * HID + c0;
            *(float4*)&vout[off]     = make_float4(o[0], o[1], o[2], o[3]);
            *(float4*)&vout[off + 4] = make_float4(o[4], o[5], o[6], o[7]);
#pragma unroll
            for (int j = 0; j < 8; j++) { ls[j] += o[j]; lq[j] += o[j] * o[j]; }
        }
    }
#pragma unroll
    for (int j = 0; j < 8; j++) {
        atomicAdd(&s_sum[c0 + j], ls[j]);
        atomicAdd(&s_sq[c0 + j],  lq[j]);
    }
    __syncthreads();
    float* stats = g_stats + layer * 2 * HID;
    if (tid < HID) {
        atomicAdd(&stats[tid], s_sum[tid]);
        atomicAdd(&stats[HID + tid], s_sq[tid]);
    }
}

// ---------------- pool: run-length segment max over g_BA --------------------
__global__ void __launch_bounds__(256) pool_kernel(
    const int* __restrict__ batch,
    const float* __restrict__ gamma, const float* __restrict__ beta)
{
    __shared__ float sc[HID], sf[HID];
    int tid = threadIdx.x;
    if (tid < HID) {
        const float* stats = g_stats + 2 * 2 * HID;
        float inv_n = 1.f / (float)N_NODES;
        float mu  = stats[tid] * inv_n;
        float var = stats[HID + tid] * inv_n - mu * mu;
        float s = gamma[tid] * rsqrtf(var + BN_EPS);
        sc[tid] = s;
        sf[tid] = beta[tid] - mu * s;
    }
    __syncthreads();

    int base = blockIdx.x * 128;
    int r = tid >> 6;
    int c = tid & 63;
    float cur = -INFINITY;
    int curg = -1;
    int lim = base + 128; if (lim > N_NODES) lim = N_NODES;
    for (int n = base + r; n < lim; n += 4) {
        int g = __ldg(&batch[n]);
        float v = g_BA[(long)n * HID + c] * sc[c] + sf[c];
        if (g != curg) {
            if (curg >= 0) atomicMaxF(&g_pooled[curg * HID + c], cur);
            curg = g; cur = v;
        } else {
            cur = fmaxf(cur, v);
        }
    }
    if (curg >= 0) atomicMaxF(&g_pooled[curg * HID + c], cur);
}

// ---------------- head ------------------------------------------------------
__global__ void __launch_bounds__(128) head_kernel(
    const float* __restrict__ lin1_w, const float* __restrict__ lin1_b,
    const float* __restrict__ lin2_w, const float* __restrict__ lin2_b,
    float* __restrict__ out)
{
    __shared__ float w1_sh[HID * HID];
    __shared__ float w2_sh[HID * OUT_F];
    __shared__ float p_sh[4][HID];
    __shared__ float h_sh[4][HID];
    int tid = threadIdx.x, warp = tid >> 5, lane = tid & 31;

    for (int i = tid; i < HID * HID / 4; i += 128)
        ((float4*)w1_sh)[i] = ((const float4*)lin1_w)[i];
    for (int i = tid; i < HID * OUT_F / 4; i += 128)
        ((float4*)w2_sh)[i] = ((const float4*)lin2_w)[i];

    int g = blockIdx.x * 4 + warp;
    float p0 = g_pooled[g * HID + lane];
    float p1 = g_pooled[g * HID + lane + 32];
    if (!isfinite(p0)) p0 = 0.f;
    if (!isfinite(p1)) p1 = 0.f;
    p_sh[warp][lane] = p0;
    p_sh[warp][lane + 32] = p1;
    __syncthreads();

    float acc0 = lin1_b[lane], acc1 = lin1_b[lane + 32];
#pragma unroll 8
    for (int k = 0; k < HID; k++) {
        float pv = p_sh[warp][k];
        acc0 += pv * w1_sh[k * HID + lane];
        acc1 += pv * w1_sh[k * HID + lane + 32];
    }
    h_sh[warp][lane]      = fmaxf(acc0, 0.f);
    h_sh[warp][lane + 32] = fmaxf(acc1, 0.f);
    __syncwarp();

    if (lane < OUT_F) {
        float acc = lin2_b[lane];
#pragma unroll 8
        for (int k = 0; k < HID; k++)
            acc += h_sh[warp][k] * w2_sh[k * OUT_F + lane];
        out[g * OUT_F + lane] = acc;
    }
}

// ---------------- launch ----------------------------------------------------
extern "C" void kernel_launch(void* const* d_in, const int* in_sizes, int n_in,
                              void* d_out, int out_size)
{
    const float* x     = (const float*)d_in[0];
    const int*   ei    = (const int*)d_in[1];    // int32 (JAX x64 disabled)
    const int*   batch = (const int*)d_in[2];
    const float* l0_w1 = (const float*)d_in[3];
    const float* l0_b1 = (const float*)d_in[4];
    const float* l0_w2 = (const float*)d_in[5];
    const float* l0_b2 = (const float*)d_in[6];
    const float* l0_g  = (const float*)d_in[7];
    const float* l0_be = (const float*)d_in[8];
    const float* ws1   = (const float*)d_in[9];
    const float* bs1   = (const float*)d_in[10];
    const float* ws2   = (const float*)d_in[11];
    const float* bs2   = (const float*)d_in[12];
    const float* gms   = (const float*)d_in[13];
    const float* bts   = (const float*)d_in[14];
    const float* lin1w = (const float*)d_in[15];
    const float* lin1b = (const float*)d_in[16];
    const float* lin2w = (const float*)d_in[17];
    const float* lin2b = (const float*)d_in[18];
    float* out = (float*)d_out;

    const int TILE_BLOCKS  = (N_NODES + 127) / 128;              // 391
    const int EDGE_BLOCKS  = (N_EDGES + 255) / 256;              // 3125
    const int SCANA_BLOCKS = (N_GRAPHS * HID + 255) / 256;       // 250

    const int SMEM_G1_L0 = (F_INPUT * HID + 128 * F_INPUT) * 4;  // 96 KB
    const int SMEM_48K   = (HID * HID + 128 * HID) * 4;          // 48 KB
    cudaFuncSetAttribute(gemm1_l0_kernel,
                         cudaFuncAttributeMaxDynamicSharedMemorySize, SMEM_G1_L0);
    cudaFuncSetAttribute(agg_gemm2_l0_kernel,
                         cudaFuncAttributeMaxDynamicSharedMemorySize, SMEM_48K);
    cudaFuncSetAttribute(fused_layer_kernel<true>,
                         cudaFuncAttributeMaxDynamicSharedMemorySize, SMEM_48K);
    cudaFuncSetAttribute(fused_layer_kernel<false>,
                         cudaFuncAttributeMaxDynamicSharedMemorySize, SMEM_48K);

    // ---- CSR build (+ pooled/stats init riding on scanA) ----
    hist_kernel<<<EDGE_BLOCKS, 256>>>(ei);
    scanA_kernel<<<SCANA_BLOCKS, 256>>>();
    scanC_kernel<<<NBLK256, 256>>>();
    fill_kernel<<<EDGE_BLOCKS, 256>>>(ei);

    // ---- layer 0: t0 = x@W1 -> BB; agg+MLP2 -> BA (stats 0) ----
    gemm1_l0_kernel<<<TILE_BLOCKS, 128, SMEM_G1_L0>>>(x, l0_w1);
    agg_gemm2_l0_kernel<<<TILE_BLOCKS, 128, SMEM_48K>>>(l0_b1, l0_w2, l0_b2);

    // ---- layer 1: BA -> BB (stats 1; BN from stats 0) ----
    fused_layer_kernel<true><<<TILE_BLOCKS, 128, SMEM_48K>>>(
        l0_g, l0_be, ws1, bs1, ws2, bs2, 0, 1);

    // ---- layer 2: BB -> BA (stats 2; BN from stats 1) ----
    fused_layer_kernel<false><<<TILE_BLOCKS, 128, SMEM_48K>>>(
        gms, bts, ws1 + HID * HID, bs1 + HID, ws2 + HID * HID, bs2 + HID, 1, 2);

    // ---- pool (BN layer 2 inline) + head ----
    pool_kernel<<<TILE_BLOCKS, 256>>>(batch, gms + HID, bts + HID);
    head_kernel<<<N_GRAPHS / 4, 128>>>(lin1w, lin1b, lin2w, lin2b, out);
}

// round 16
// speedup vs baseline: 1.0694x; 1.0694x over previous
#include <cuda_runtime.h>
#include <math.h>

#define N_NODES  50000
#define N_EDGES  800000
#define N_GRAPHS 1000
#define F_INPUT  128
#define HID      64
#define OUT_F    16
#define BN_EPS   1e-5f
#define NBLK256  ((N_NODES + 255) / 256)   // 196
#define G1_THREADS_TOTAL (391 * 128)       // gemm1_l0 grid * block

// ---------------- scratch (static device globals; no allocation) ------------
// g_deg relies on static zero-init for the first call; scanC re-zeroes it
// after reading (same work every call, deterministic).
__device__ float g_BA[N_NODES * HID];      // ping buffer
__device__ float g_BB[N_NODES * HID];      // pong buffer
__device__ float g_stats[3 * 2 * HID];     // per-layer sum, sumsq
__device__ float g_pooled[N_GRAPHS * HID]; // segment max
// CSR scratch
__device__ int g_deg[N_NODES];
__device__ int g_off[N_NODES + 1];
__device__ int g_cur[N_NODES];
__device__ int g_csr[N_EDGES];
__device__ int g_bsum[NBLK256];

// ---------------- helpers ---------------------------------------------------
__device__ __forceinline__ void atomicMaxF(float* addr, float val) {
    if (val >= 0.f) atomicMax((int*)addr, __float_as_int(val));
    else            atomicMin((unsigned int*)addr, __float_as_uint(val));
}
__device__ __forceinline__ void add4(float4& a, const float4 b) {
    a.x += b.x; a.y += b.y; a.z += b.z; a.w += b.w;
}

// ---------------- CSR build -------------------------------------------------
// scanA: per-block degree sums (blocks < NBLK256) + init pooled/stats.
__global__ void scanA_kernel() {
    __shared__ int sh[256];
    int tid = threadIdx.x;
    int gi = blockIdx.x * 256 + tid;
    if (gi < N_GRAPHS * HID) g_pooled[gi] = -INFINITY;
    if (gi < 3 * 2 * HID) g_stats[gi] = 0.f;
    if (blockIdx.x >= NBLK256) return;
    int n = blockIdx.x * 256 + tid;
    sh[tid] = (n < N_NODES) ? g_deg[n] : 0;
    __syncthreads();
    for (int s = 128; s > 0; s >>= 1) {
        if (tid < s) sh[tid] += sh[tid + s];
        __syncthreads();
    }
    if (tid == 0) g_bsum[blockIdx.x] = sh[0];
}
// scanC: per-node offsets; zeroes g_deg after reading (reset for next call).
__global__ void scanC_kernel() {
    __shared__ int sh[256];
    __shared__ int boff_sh;
    int tid = threadIdx.x;
    int part = 0;
    for (int j = tid; j < blockIdx.x; j += 256) part += g_bsum[j];
    sh[tid] = part;
    __syncthreads();
    for (int s = 128; s > 0; s >>= 1) {
        if (tid < s) sh[tid] += sh[tid + s];
        __syncthreads();
    }
    if (tid == 0) boff_sh = sh[0];
    __syncthreads();
    int boff = boff_sh;
    int n = blockIdx.x * 256 + tid;
    int v = (n < N_NODES) ? g_deg[n] : 0;
    if (n < N_NODES) g_deg[n] = 0;       // reset for next call
    sh[tid] = v;
    __syncthreads();
    for (int d = 1; d < 256; d <<= 1) {
        int t = (tid >= d) ? sh[tid - d] : 0;
        __syncthreads();
        sh[tid] += t;
        __syncthreads();
    }
    if (n < N_NODES) {
        int off = boff + sh[tid] - v;
        g_off[n] = off;
        g_cur[n] = off;
    }
    if (blockIdx.x == NBLK256 - 1 && tid == 255)
        g_off[N_NODES] = boff + sh[255];
}
__global__ void fill_kernel(const int* __restrict__ ei) {
    int e = blockIdx.x * blockDim.x + threadIdx.x;
    if (e >= N_EDGES) return;
    int s = __ldg(&ei[e]);
    int d = __ldg(&ei[N_EDGES + e]);
    int pos = atomicAdd(&g_cur[d], 1);
    g_csr[pos] = s;
}

// ---------------- gemm1_L0 + hist: B1 = x @ l0_w1, deg histogram ------------
// 128-row tile, 128 threads, 8x8 register blocking (R11 body) with the edge
// degree histogram fused at the top (fire-and-forget REDG drains under GEMM).
__global__ void __launch_bounds__(128) gemm1_l0_kernel(
    const float* __restrict__ h, const float* __restrict__ w,
    const int* __restrict__ ei)
{
    extern __shared__ float smem[];
    float* w_sh = smem;                     // [128][64]
    float* h_sh = smem + F_INPUT * HID;     // [128][128]
    int tid = threadIdx.x;

    // fused histogram: grid-stride over dst indices
    {
        int gtid = blockIdx.x * 128 + tid;
        for (int e = gtid; e < N_EDGES; e += G1_THREADS_TOTAL)
            atomicAdd(&g_deg[__ldg(&ei[N_EDGES + e])], 1);
    }

    for (int i = tid; i < F_INPUT * HID / 4; i += 128)
        ((float4*)w_sh)[i] = ((const float4*)w)[i];

    int rowbase = blockIdx.x * 128;
    int nrows = N_NODES - rowbase; if (nrows > 128) nrows = 128;
    const float4* hbase = (const float4*)(h + (long)rowbase * F_INPUT);
    for (int i = tid; i < 128 * F_INPUT / 4; i += 128) {
        int r = i / (F_INPUT / 4);
        ((float4*)h_sh)[i] = (r < nrows) ? hbase[i] : make_float4(0.f, 0.f, 0.f, 0.f);
    }
    __syncthreads();

    int rg = tid >> 3, cg = tid & 7;
    int r0 = rg * 8, c0 = cg * 8;
    float acc[8][8];
#pragma unroll
    for (int r = 0; r < 8; r++)
#pragma unroll
        for (int j = 0; j < 8; j++) acc[r][j] = 0.f;

    for (int k = 0; k < F_INPUT; k += 4) {
        float4 av[8];
#pragma unroll
        for (int r = 0; r < 8; r++)
            av[r] = *(const float4*)&h_sh[(r0 + r) * F_INPUT + k];
#pragma unroll
        for (int kk = 0; kk < 4; kk++) {
            float4 w0 = *(const float4*)&w_sh[(k + kk) * HID + c0];
            float4 w1 = *(const float4*)&w_sh[(k + kk) * HID + c0 + 4];
#pragma unroll
            for (int r = 0; r < 8; r++) {
                float a = (kk == 0) ? av[r].x : (kk == 1) ? av[r].y
                         : (kk == 2) ? av[r].z : av[r].w;
                acc[r][0] += a * w0.x; acc[r][1] += a * w0.y;
                acc[r][2] += a * w0.z; acc[r][3] += a * w0.w;
                acc[r][4] += a * w1.x; acc[r][5] += a * w1.y;
                acc[r][6] += a * w1.z; acc[r][7] += a * w1.w;
            }
        }
    }
#pragma unroll
    for (int r = 0; r < 8; r++) {
        if (r0 + r < nrows) {
            long off = (long)(rowbase + r0 + r) * HID + c0;
            *(float4*)&g_BB[off]     = make_float4(acc[r][0], acc[r][1], acc[r][2], acc[r][3]);
            *(float4*)&g_BB[off + 4] = make_float4(acc[r][4], acc[r][5], acc[r][6], acc[r][7]);
        }
    }
}

// ---------------- layer-0 fused agg + gemm2 (R11-exact) ---------------------
__global__ void __launch_bounds__(128) agg_gemm2_l0_kernel(
    const float* __restrict__ b1, const float* __restrict__ w2,
    const float* __restrict__ b2)
{
    extern __shared__ float smem[];
    float* w_sh = smem;                 // [64][64]
    float* u_sh = smem + HID * HID;     // [128][64]
    __shared__ float s_sum[HID];
    __shared__ float s_sq[HID];
    int tid = threadIdx.x;

    for (int i = tid; i < HID * HID / 4; i += 128)
        ((float4*)w_sh)[i] = ((const float4*)w2)[i];
    if (tid < HID) { s_sum[tid] = 0.f; s_sq[tid] = 0.f; }

    int rowbase = blockIdx.x * 128;
    int nrows = N_NODES - rowbase; if (nrows > 128) nrows = 128;

    // gather: 1024 tasks (128 rows x 8 slices), 8 per thread
    for (int it = 0; it < 8; it++) {
        int task = it * 128 + tid;
        int row = task >> 3;
        int c = (task & 7) * 8;
        float4 a0 = make_float4(0.f, 0.f, 0.f, 0.f), a1 = a0;
        if (row < nrows) {
            int node = rowbase + row;
            long base = (long)node * HID + c;
            a0 = *(const float4*)&g_BB[base];
            a1 = *(const float4*)&g_BB[base + 4];
            int p = g_off[node], end = g_off[node + 1];
            for (; p + 2 <= end; p += 2) {
                int s0 = __ldg(&g_csr[p]);
                int s1 = __ldg(&g_csr[p + 1]);
                const float4* t0 = (const float4*)(g_BB + (long)s0 * HID + c);
                const float4* t1 = (const float4*)(g_BB + (long)s1 * HID + c);
                float4 v00 = __ldg(t0), v01 = __ldg(t0 + 1);
                float4 v10 = __ldg(t1), v11 = __ldg(t1 + 1);
                add4(a0, v00); add4(a1, v01);
                add4(a0, v10); add4(a1, v11);
            }
            if (p < end) {
                int s0 = __ldg(&g_csr[p]);
                const float4* t0 = (const float4*)(g_BB + (long)s0 * HID + c);
                add4(a0, __ldg(t0)); add4(a1, __ldg(t0 + 1));
            }
            float4 bb0 = *(const float4*)&b1[c];
            float4 bb1 = *(const float4*)&b1[c + 4];
            a0.x = fmaxf(a0.x + bb0.x, 0.f); a0.y = fmaxf(a0.y + bb0.y, 0.f);
            a0.z = fmaxf(a0.z + bb0.z, 0.f); a0.w = fmaxf(a0.w + bb0.w, 0.f);
            a1.x = fmaxf(a1.x + bb1.x, 0.f); a1.y = fmaxf(a1.y + bb1.y, 0.f);
            a1.z = fmaxf(a1.z + bb1.z, 0.f); a1.w = fmaxf(a1.w + bb1.w, 0.f);
        }
        *(float4*)&u_sh[row * HID + c]     = a0;
        *(float4*)&u_sh[row * HID + c + 4] = a1;
    }
    __syncthreads();

    // GEMM2 (8x8 per thread)
    int rg = tid >> 3, cg = tid & 7;
    int r0 = rg * 8, c0 = cg * 8;
    float acc[8][8];
#pragma unroll
    for (int r = 0; r < 8; r++)
#pragma unroll
        for (int j = 0; j < 8; j++) acc[r][j] = 0.f;

    for (int k = 0; k < HID; k += 4) {
        float4 av[8];
#pragma unroll
        for (int r = 0; r < 8; r++)
            av[r] = *(const float4*)&u_sh[(r0 + r) * HID + k];
#pragma unroll
        for (int kk = 0; kk < 4; kk++) {
            float4 w0 = *(const float4*)&w_sh[(k + kk) * HID + c0];
            float4 w1 = *(const float4*)&w_sh[(k + kk) * HID + c0 + 4];
#pragma unroll
            for (int r = 0; r < 8; r++) {
                float a = (kk == 0) ? av[r].x : (kk == 1) ? av[r].y
                         : (kk == 2) ? av[r].z : av[r].w;
                acc[r][0] += a * w0.x; acc[r][1] += a * w0.y;
                acc[r][2] += a * w0.z; acc[r][3] += a * w0.w;
                acc[r][4] += a * w1.x; acc[r][5] += a * w1.y;
                acc[r][6] += a * w1.z; acc[r][7] += a * w1.w;
            }
        }
    }

    float4 bb0 = *(const float4*)&b2[c0];
    float4 bb1 = *(const float4*)&b2[c0 + 4];
    float ls[8] = {0,0,0,0,0,0,0,0};
    float lq[8] = {0,0,0,0,0,0,0,0};
#pragma unroll
    for (int r = 0; r < 8; r++) {
        if (r0 + r < nrows) {
            float o[8];
            o[0] = fmaxf(acc[r][0] + bb0.x, 0.f); o[1] = fmaxf(acc[r][1] + bb0.y, 0.f);
            o[2] = fmaxf(acc[r][2] + bb0.z, 0.f); o[3] = fmaxf(acc[r][3] + bb0.w, 0.f);
            o[4] = fmaxf(acc[r][4] + bb1.x, 0.f); o[5] = fmaxf(acc[r][5] + bb1.y, 0.f);
            o[6] = fmaxf(acc[r][6] + bb1.z, 0.f); o[7] = fmaxf(acc[r][7] + bb1.w, 0.f);
            long off = (long)(rowbase + r0 + r) * HID + c0;
            *(float4*)&g_BA[off]     = make_float4(o[0], o[1], o[2], o[3]);
            *(float4*)&g_BA[off + 4] = make_float4(o[4], o[5], o[6], o[7]);
#pragma unroll
            for (int j = 0; j < 8; j++) { ls[j] += o[j]; lq[j] += o[j] * o[j]; }
        }
    }
#pragma unroll
    for (int j = 0; j < 8; j++) {
        atomicAdd(&s_sum[c0 + j], ls[j]);
        atomicAdd(&s_sq[c0 + j],  lq[j]);
    }
    __syncthreads();
    if (tid < HID) {
        atomicAdd(&g_stats[tid], s_sum[tid]);
        atomicAdd(&g_stats[HID + tid], s_sq[tid]);
    }
}

// ---------------- fused layer (layers 1,2) — R11-exact ----------------------
// u = relu( aggv @ (sc⊙W1) + (1+deg_r)·(sf@W1)_c + b1_c )
// vout = relu( u @ W2 + b2 ) ; stats[layer]
template <bool IN_IS_A>
__global__ void __launch_bounds__(128) fused_layer_kernel(
    const float* __restrict__ gamma, const float* __restrict__ beta,
    const float* __restrict__ w1, const float* __restrict__ b1,
    const float* __restrict__ w2, const float* __restrict__ b2,
    int stats_layer, int layer)
{
    extern __shared__ float smem[];
    float* w_sh = smem;                 // [64][64] : W1f, later W2
    float* t_sh = smem + HID * HID;     // [128][64]: aggv, later u
    __shared__ float sc[HID], sf[HID], sfw1[HID];
    __shared__ float degs[128];
    __shared__ float s_sum[HID];
    __shared__ float s_sq[HID];
    int tid = threadIdx.x;

    const float* vin = IN_IS_A ? g_BA : g_BB;
    float* vout      = IN_IS_A ? g_BB : g_BA;

    if (tid < HID) {
        const float* stats = g_stats + stats_layer * 2 * HID;
        float inv_n = 1.f / (float)N_NODES;
        float mu  = stats[tid] * inv_n;
        float var = stats[HID + tid] * inv_n - mu * mu;
        float s = gamma[tid] * rsqrtf(var + BN_EPS);
        sc[tid] = s;
        sf[tid] = beta[tid] - mu * s;
        s_sum[tid] = 0.f; s_sq[tid] = 0.f;
    }
    __syncthreads();

    for (int i = tid; i < HID * HID / 4; i += 128) {
        float4 v = ((const float4*)w1)[i];
        float s = sc[i >> 4];
        v.x *= s; v.y *= s; v.z *= s; v.w *= s;
        ((float4*)w_sh)[i] = v;
    }
    if (tid < HID) {
        float b = 0.f;
#pragma unroll 8
        for (int k = 0; k < HID; k++)
            b += sf[k] * __ldg(&w1[k * HID + tid]);
        sfw1[tid] = b;
    }

    int rowbase = blockIdx.x * 128;
    int nrows = N_NODES - rowbase; if (nrows > 128) nrows = 128;

    // gather RAW aggv into t_sh; record deg
    for (int it = 0; it < 8; it++) {
        int task = it * 128 + tid;
        int row = task >> 3;
        int c = (task & 7) * 8;
        float4 a0 = make_float4(0.f, 0.f, 0.f, 0.f), a1 = a0;
        if (row < nrows) {
            int node = rowbase + row;
            long base = (long)node * HID + c;
            a0 = *(const float4*)&vin[base];
            a1 = *(const float4*)&vin[base + 4];
            int p = g_off[node], end = g_off[node + 1];
            if (c == 0) degs[row] = (float)(1 + end - p);
            for (; p + 2 <= end; p += 2) {
                int s0 = __ldg(&g_csr[p]);
                int s1 = __ldg(&g_csr[p + 1]);
                const float4* t0 = (const float4*)(vin + (long)s0 * HID + c);
                const float4* t1 = (const float4*)(vin + (long)s1 * HID + c);
                float4 v00 = __ldg(t0), v01 = __ldg(t0 + 1);
                float4 v10 = __ldg(t1), v11 = __ldg(t1 + 1);
                add4(a0, v00); add4(a1, v01);
                add4(a0, v10); add4(a1, v11);
            }
            if (p < end) {
                int s0 = __ldg(&g_csr[p]);
                const float4* t0 = (const float4*)(vin + (long)s0 * HID + c);
                add4(a0, __ldg(t0)); add4(a1, __ldg(t0 + 1));
            }
        }
        *(float4*)&t_sh[row * HID + c]     = a0;
        *(float4*)&t_sh[row * HID + c + 4] = a1;
    }
    __syncthreads();

    int rg = tid >> 3, cg = tid & 7;
    int r0 = rg * 8, c0 = cg * 8;

    // GEMM1
    float acc[8][8];
#pragma unroll
    for (int r = 0; r < 8; r++)
#pragma unroll
        for (int j = 0; j < 8; j++) acc[r][j] = 0.f;

    for (int k = 0; k < HID; k += 4) {
        float4 av[8];
#pragma unroll
        for (int r = 0; r < 8; r++)
            av[r] = *(const float4*)&t_sh[(r0 + r) * HID + k];
#pragma unroll
        for (int kk = 0; kk < 4; kk++) {
            float4 w0 = *(const float4*)&w_sh[(k + kk) * HID + c0];
            float4 w1v = *(const float4*)&w_sh[(k + kk) * HID + c0 + 4];
#pragma unroll
            for (int r = 0; r < 8; r++) {
                float a = (kk == 0) ? av[r].x : (kk == 1) ? av[r].y
                         : (kk == 2) ? av[r].z : av[r].w;
                acc[r][0] += a * w0.x;  acc[r][1] += a * w0.y;
                acc[r][2] += a * w0.z;  acc[r][3] += a * w0.w;
                acc[r][4] += a * w1v.x; acc[r][5] += a * w1v.y;
                acc[r][6] += a * w1v.z; acc[r][7] += a * w1v.w;
            }
        }
    }
    float4 p0 = *(const float4*)&sfw1[c0];
    float4 p1 = *(const float4*)&sfw1[c0 + 4];
    float4 q0 = *(const float4*)&b1[c0];
    float4 q1 = *(const float4*)&b1[c0 + 4];
    float u[8][8];
#pragma unroll
    for (int r = 0; r < 8; r++) {
        float n = degs[r0 + r];
        u[r][0] = fmaxf(acc[r][0] + n * p0.x + q0.x, 0.f);
        u[r][1] = fmaxf(acc[r][1] + n * p0.y + q0.y, 0.f);
        u[r][2] = fmaxf(acc[r][2] + n * p0.z + q0.z, 0.f);
        u[r][3] = fmaxf(acc[r][3] + n * p0.w + q0.w, 0.f);
        u[r][4] = fmaxf(acc[r][4] + n * p1.x + q1.x, 0.f);
        u[r][5] = fmaxf(acc[r][5] + n * p1.y + q1.y, 0.f);
        u[r][6] = fmaxf(acc[r][6] + n * p1.z + q1.z, 0.f);
        u[r][7] = fmaxf(acc[r][7] + n * p1.w + q1.w, 0.f);
    }
    __syncthreads();

#pragma unroll
    for (int r = 0; r < 8; r++) {
        *(float4*)&t_sh[(r0 + r) * HID + c0]     = make_float4(u[r][0], u[r][1], u[r][2], u[r][3]);
        *(float4*)&t_sh[(r0 + r) * HID + c0 + 4] = make_float4(u[r][4], u[r][5], u[r][6], u[r][7]);
    }
    for (int i = tid; i < HID * HID / 4; i += 128)
        ((float4*)w_sh)[i] = ((const float4*)w2)[i];
    __syncthreads();

    // GEMM2
#pragma unroll
    for (int r = 0; r < 8; r++)
#pragma unroll
        for (int j = 0; j < 8; j++) acc[r][j] = 0.f;

    for (int k = 0; k < HID; k += 4) {
        float4 av[8];
#pragma unroll
        for (int r = 0; r < 8; r++)
            av[r] = *(const float4*)&t_sh[(r0 + r) * HID + k];
#pragma unroll
        for (int kk = 0; kk < 4; kk++) {
            float4 w0 = *(const float4*)&w_sh[(k + kk) * HID + c0];
            float4 w1v = *(const float4*)&w_sh[(k + kk) * HID + c0 + 4];
#pragma unroll
            for (int r = 0; r < 8; r++) {
                float a = (kk == 0) ? av[r].x : (kk == 1) ? av[r].y
                         : (kk == 2) ? av[r].z : av[r].w;
                acc[r][0] += a * w0.x;  acc[r][1] += a * w0.y;
                acc[r][2] += a * w0.z;  acc[r][3] += a * w0.w;
                acc[r][4] += a * w1v.x; acc[r][5] += a * w1v.y;
                acc[r][6] += a * w1v.z; acc[r][7] += a * w1v.w;
            }
        }
    }

    float4 bb0 = *(const float4*)&b2[c0];
    float4 bb1 = *(const float4*)&b2[c0 + 4];
    float ls[8] = {0,0,0,0,0,0,0,0};
    float lq[8] = {0,0,0,0,0,0,0,0};
#pragma unroll
    for (int r = 0; r < 8; r++) {
        if (r0 + r < nrows) {
            float o[8];
            o[0] = fmaxf(acc[r][0] + bb0.x, 0.f); o[1] = fmaxf(acc[r][1] + bb0.y, 0.f);
            o[2] = fmaxf(acc[r][2] + bb0.z, 0.f); o[3] = fmaxf(acc[r][3] + bb0.w, 0.f);
            o[4] = fmaxf(acc[r][4] + bb1.x, 0.f); o[5] = fmaxf(acc[r][5] + bb1.y, 0.f);
            o[6] = fmaxf(acc[r][6] + bb1.z, 0.f); o[7] = fmaxf(acc[r][7] + bb1.w, 0.f);
            long off = (long)(rowbase + r0 + r) * HID + c0;
            *(float4*)&vout[off]     = make_float4(o[0], o[1], o[2], o[3]);
            *(float4*)&vout[off + 4] = make_float4(o[4], o[5], o[6], o[7]);
#pragma unroll
            for (int j = 0; j < 8; j++) { ls[j] += o[j]; lq[j] += o[j] * o[j]; }
        }
    }
#pragma unroll
    for (int j = 0; j < 8; j++) {
        atomicAdd(&s_sum[c0 + j], ls[j]);
        atomicAdd(&s_sq[c0 + j],  lq[j]);
    }
    __syncthreads();
    float* stats = g_stats + layer * 2 * HID;
    if (tid < HID) {
        atomicAdd(&stats[tid], s_sum[tid]);
        atomicAdd(&stats[HID + tid], s_sq[tid]);
    }
}

// ---------------- pool: run-length segment max over g_BA --------------------
__global__ void __launch_bounds__(256) pool_kernel(
    const int* __restrict__ batch,
    const float* __restrict__ gamma, const float* __restrict__ beta)
{
    __shared__ float sc[HID], sf[HID];
    int tid = threadIdx.x;
    if (tid < HID) {
        const float* stats = g_stats + 2 * 2 * HID;
        float inv_n = 1.f / (float)N_NODES;
        float mu  = stats[tid] * inv_n;
        float var = stats[HID + tid] * inv_n - mu * mu;
        float s = gamma[tid] * rsqrtf(var + BN_EPS);
        sc[tid] = s;
        sf[tid] = beta[tid] - mu * s;
    }
    __syncthreads();

    int base = blockIdx.x * 128;
    int r = tid >> 6;
    int c = tid & 63;
    float cur = -INFINITY;
    int curg = -1;
    int lim = base + 128; if (lim > N_NODES) lim = N_NODES;
    for (int n = base + r; n < lim; n += 4) {
        int g = __ldg(&batch[n]);
        float v = g_BA[(long)n * HID + c] * sc[c] + sf[c];
        if (g != curg) {
            if (curg >= 0) atomicMaxF(&g_pooled[curg * HID + c], cur);
            curg = g; cur = v;
        } else {
            cur = fmaxf(cur, v);
        }
    }
    if (curg >= 0) atomicMaxF(&g_pooled[curg * HID + c], cur);
}

// ---------------- head ------------------------------------------------------
__global__ void __launch_bounds__(128) head_kernel(
    const float* __restrict__ lin1_w, const float* __restrict__ lin1_b,
    const float* __restrict__ lin2_w, const float* __restrict__ lin2_b,
    float* __restrict__ out)
{
    __shared__ float w1_sh[HID * HID];
    __shared__ float w2_sh[HID * OUT_F];
    __shared__ float p_sh[4][HID];
    __shared__ float h_sh[4][HID];
    int tid = threadIdx.x, warp = tid >> 5, lane = tid & 31;

    for (int i = tid; i < HID * HID / 4; i += 128)
        ((float4*)w1_sh)[i] = ((const float4*)lin1_w)[i];
    for (int i = tid; i < HID * OUT_F / 4; i += 128)
        ((float4*)w2_sh)[i] = ((const float4*)lin2_w)[i];

    int g = blockIdx.x * 4 + warp;
    float p0 = g_pooled[g * HID + lane];
    float p1 = g_pooled[g * HID + lane + 32];
    if (!isfinite(p0)) p0 = 0.f;
    if (!isfinite(p1)) p1 = 0.f;
    p_sh[warp][lane] = p0;
    p_sh[warp][lane + 32] = p1;
    __syncthreads();

    float acc0 = lin1_b[lane], acc1 = lin1_b[lane + 32];
#pragma unroll 8
    for (int k = 0; k < HID; k++) {
        float pv = p_sh[warp][k];
        acc0 += pv * w1_sh[k * HID + lane];
        acc1 += pv * w1_sh[k * HID + lane + 32];
    }
    h_sh[warp][lane]      = fmaxf(acc0, 0.f);
    h_sh[warp][lane + 32] = fmaxf(acc1, 0.f);
    __syncwarp();

    if (lane < OUT_F) {
        float acc = lin2_b[lane];
#pragma unroll 8
        for (int k = 0; k < HID; k++)
            acc += h_sh[warp][k] * w2_sh[k * OUT_F + lane];
        out[g * OUT_F + lane] = acc;
    }
}

// ---------------- launch ----------------------------------------------------
extern "C" void kernel_launch(void* const* d_in, const int* in_sizes, int n_in,
                              void* d_out, int out_size)
{
    const float* x     = (const float*)d_in[0];
    const int*   ei    = (const int*)d_in[1];    // int32 (JAX x64 disabled)
    const int*   batch = (const int*)d_in[2];
    const float* l0_w1 = (const float*)d_in[3];
    const float* l0_b1 = (const float*)d_in[4];
    const float* l0_w2 = (const float*)d_in[5];
    const float* l0_b2 = (const float*)d_in[6];
    const float* l0_g  = (const float*)d_in[7];
    const float* l0_be = (const float*)d_in[8];
    const float* ws1   = (const float*)d_in[9];
    const float* bs1   = (const float*)d_in[10];
    const float* ws2   = (const float*)d_in[11];
    const float* bs2   = (const float*)d_in[12];
    const float* gms   = (const float*)d_in[13];
    const float* bts   = (const float*)d_in[14];
    const float* lin1w = (const float*)d_in[15];
    const float* lin1b = (const float*)d_in[16];
    const float* lin2w = (const float*)d_in[17];
    const float* lin2b = (const float*)d_in[18];
    float* out = (float*)d_out;

    const int TILE_BLOCKS  = (N_NODES + 127) / 128;              // 391
    const int EDGE_BLOCKS  = (N_EDGES + 255) / 256;              // 3125
    const int SCANA_BLOCKS = (N_GRAPHS * HID + 255) / 256;       // 250

    const int SMEM_G1_L0 = (F_INPUT * HID + 128 * F_INPUT) * 4;  // 96 KB
    const int SMEM_48K   = (HID * HID + 128 * HID) * 4;          // 48 KB
    cudaFuncSetAttribute(gemm1_l0_kernel,
                         cudaFuncAttributeMaxDynamicSharedMemorySize, SMEM_G1_L0);
    cudaFuncSetAttribute(agg_gemm2_l0_kernel,
                         cudaFuncAttributeMaxDynamicSharedMemorySize, SMEM_48K);
    cudaFuncSetAttribute(fused_layer_kernel<true>,
                         cudaFuncAttributeMaxDynamicSharedMemorySize, SMEM_48K);
    cudaFuncSetAttribute(fused_layer_kernel<false>,
                         cudaFuncAttributeMaxDynamicSharedMemorySize, SMEM_48K);

    // ---- layer-0 GEMM1 with fused degree histogram ----
    gemm1_l0_kernel<<<TILE_BLOCKS, 128, SMEM_G1_L0>>>(x, l0_w1, ei);

    // ---- CSR build (pooled/stats init rides scanA; deg reset rides scanC) ----
    scanA_kernel<<<SCANA_BLOCKS, 256>>>();
    scanC_kernel<<<NBLK256, 256>>>();
    fill_kernel<<<EDGE_BLOCKS, 256>>>(ei);

    // ---- layer 0 agg + MLP2 -> BA (stats 0) ----
    agg_gemm2_l0_kernel<<<TILE_BLOCKS, 128, SMEM_48K>>>(l0_b1, l0_w2, l0_b2);

    // ---- layer 1: BA -> BB (stats 1; BN from stats 0) ----
    fused_layer_kernel<true><<<TILE_BLOCKS, 128, SMEM_48K>>>(
        l0_g, l0_be, ws1, bs1, ws2, bs2, 0, 1);

    // ---- layer 2: BB -> BA (stats 2; BN from stats 1) ----
    fused_layer_kernel<false><<<TILE_BLOCKS, 128, SMEM_48K>>>(
        gms, bts, ws1 + HID * HID, bs1 + HID, ws2 + HID * HID, bs2 + HID, 1, 2);

    // ---- pool (BN layer 2 inline) + head ----
    pool_kernel<<<TILE_BLOCKS, 256>>>(batch, gms + HID, bts + HID);
    head_kernel<<<N_GRAPHS / 4, 128>>>(lin1w, lin1b, lin2w, lin2b, out);
}